// round 3
// baseline (speedup 1.0000x reference)
#include <cuda_runtime.h>

#define PNUM 32
#define INF  7
#define D2   64
#define OUTF 4096           // 2*D2*PNUM floats per voxel
#define VPW  4              // voxels per warp
#define FULLM 0xffffffffu

__global__ __launch_bounds__(128, 8)
void vfe_kernel(const float* __restrict__ x,
                const float* __restrict__ W,
                const float* __restrict__ bias,
                float* __restrict__ out,
                int B)
{
    // Warp-private staging: x rows padded to 8 floats, plus global vector.
    __shared__ float swx[4][PNUM * 8];
    __shared__ float swg[4][D2];

    const int t    = threadIdx.x;
    const int wid  = t >> 5;
    const int lane = t & 31;
    const int dg   = lane & 15;     // 4 output dims [4*dg, 4*dg+4)
    const int ph   = lane >> 4;     // point parity

    float* __restrict__ sx = swx[wid];
    float* __restrict__ sg = swg[wid];

    // Weights + bias for this lane's 4 dims, register-resident for all voxels.
    float w[4][INF], bb[4];
    #pragma unroll
    for (int k = 0; k < 4; k++) {
        const int d = dg * 4 + k;
        bb[k] = bias[d];
        #pragma unroll
        for (int i = 0; i < INF; i++) w[k][i] = W[d * INF + i];
    }

    const int gw = blockIdx.x * 4 + wid;   // global warp id
    const int v0 = gw * VPW;

    // Prologue: load voxel v0's x (lane owns point `lane`, 7 floats).
    float xr[INF];
    if (v0 < B) {
        const float* xv = x + (size_t)v0 * (PNUM * INF) + lane * INF;
        #pragma unroll
        for (int i = 0; i < INF; i++) xr[i] = xv[i];
    }

    #pragma unroll 1
    for (int it = 0; it < VPW; it++) {
        const int v = v0 + it;
        if (v >= B) break;

        // Commit prefetched x into the warp's shared slab.
        __syncwarp();                       // prior voxel's LDS reads done
        #pragma unroll
        for (int i = 0; i < INF; i++) sx[lane * 8 + i] = xr[i];
        __syncwarp();

        // Prefetch next voxel's x (overlaps the whole compute+store phase).
        if (it + 1 < VPW && v + 1 < B) {
            const float* xn = x + (size_t)(v + 1) * (PNUM * INF) + lane * INF;
            #pragma unroll
            for (int i = 0; i < INF; i++) xr[i] = xn[i];
        }

        float* ov = out + (size_t)v * OUTF;

        #pragma unroll 4
        for (int j2 = 0; j2 < 16; j2++) {
            const int p = 2 * j2 + ph;
            // Broadcast LDS.128: half-warp reads one row each (2 addrs, no conflict).
            const float4 a0 = *(const float4*)(sx + p * 8);
            const float4 a1 = *(const float4*)(sx + p * 8 + 4);

            float acc[4];
            #pragma unroll
            for (int k = 0; k < 4; k++) {
                float a = bb[k];
                a = fmaf(a0.x, w[k][0], a);
                a = fmaf(a0.y, w[k][1], a);
                a = fmaf(a0.z, w[k][2], a);
                a = fmaf(a0.w, w[k][3], a);
                a = fmaf(a1.x, w[k][4], a);
                a = fmaf(a1.y, w[k][5], a);
                a = fmaf(a1.z, w[k][6], a);
                acc[k] = a;
            }

            // Local half of row p: two 256B coalesced runs per STG.128.
            *(float4*)(ov + p * 128 + dg * 4) =
                make_float4(acc[0], acc[1], acc[2], acc[3]);

            // Half-row max within the natural 8-lane group.
            float m = fmaxf(fmaxf(acc[0], acc[1]), fmaxf(acc[2], acc[3]));
            m = fmaxf(m, __shfl_xor_sync(FULLM, m, 1));
            m = fmaxf(m, __shfl_xor_sync(FULLM, m, 2));
            m = fmaxf(m, __shfl_xor_sync(FULLM, m, 4));
            // group (ph, half): lanes {0,8,16,24} hold g[4*j2 + lane/8]
            if ((lane & 7) == 0) sg[4 * j2 + (lane >> 3)] = m;
        }

        __syncwarp();
        const float4 gv = *(const float4*)(sg + dg * 4);

        // Broadcast half of every row (same coalesced store pattern).
        #pragma unroll
        for (int jj = 0; jj < 16; jj++) {
            const int p = 2 * jj + ph;
            *(float4*)(ov + p * 128 + 64 + dg * 4) = gv;
        }
    }
}

extern "C" void kernel_launch(void* const* d_in, const int* in_sizes, int n_in,
                              void* d_out, int out_size)
{
    const float* x = (const float*)d_in[0];
    const float* W = (const float*)d_in[1];
    const float* b = (const float*)d_in[2];
    float* out     = (float*)d_out;

    const int B = in_sizes[0] / (PNUM * INF);        // 32768
    const int warps = (B + VPW - 1) / VPW;           // 8192
    const int grid  = (warps + 3) / 4;               // 2048 blocks of 128
    vfe_kernel<<<grid, 128>>>(x, W, b, out, B);
}

// round 4
// speedup vs baseline: 1.0442x; 1.0442x over previous
#include <cuda_runtime.h>

#define PNUM 32
#define INF  7
#define D2   64
#define OUTF 4096   // 2*D2*PNUM floats per voxel
#define VPB  4      // voxels per block

__global__ __launch_bounds__(128, 8)
void vfe_kernel(const float* __restrict__ x,
                const float* __restrict__ W,
                const float* __restrict__ bias,
                float* __restrict__ out,
                int B)
{
    __shared__ float sx[2][PNUM * 8];   // double-buffered staged x (rows padded to 8)
    __shared__ float sglob[2][D2];      // double-buffered global feature vector

    const int t   = threadIdx.x;
    const int dg  = t & 15;             // dim group: dims [4*dg, 4*dg+4)
    const int pgr = t >> 4;             // point group: points [4*pgr, 4*pgr+4)

    // Per-thread weights + bias in registers, reused across all voxels.
    float w[4][INF], bb[4];
    #pragma unroll
    for (int k = 0; k < 4; k++) {
        const int d = dg * 4 + k;
        bb[k] = bias[d];
        #pragma unroll
        for (int i = 0; i < INF; i++) w[k][i] = W[d * INF + i];
    }

    // Hoisted prefetch addressing (t is loop-invariant).
    const int i0 = t;                       // always < 224
    const int r0 = i0 / INF, c0 = i0 - r0 * INF;
    const int i1 = t + 128;                 // < 224 only for t < 96
    const int r1 = i1 / INF, c1 = i1 - r1 * INF;
    const bool do1 = (i1 < PNUM * INF);

    const int v0 = blockIdx.x * VPB;

    // Prologue: stage voxel v0 into buffer 0.
    if (v0 < B) {
        const float* xv = x + (size_t)v0 * (PNUM * INF);
        sx[0][r0 * 8 + c0] = xv[i0];
        if (do1) sx[0][r1 * 8 + c1] = xv[i1];
    }
    __syncthreads();

    #pragma unroll 1
    for (int it = 0; it < VPB; it++) {
        const int v = v0 + it;
        if (v >= B) break;
        const int c = it & 1;

        // Prefetch next voxel's x into registers (overlaps with compute+stores).
        float pf0 = 0.f, pf1 = 0.f;
        const bool has_next = (it + 1 < VPB) && (v + 1 < B);
        if (has_next) {
            const float* xn = x + (size_t)(v + 1) * (PNUM * INF);
            pf0 = xn[i0];
            if (do1) pf1 = xn[i1];
        }

        float* ov = out + (size_t)v * OUTF;

        #pragma unroll
        for (int j = 0; j < 4; j++) {
            const int p = pgr * 4 + j;
            const float4 a0 = *(const float4*)(&sx[c][p * 8]);
            const float4 a1 = *(const float4*)(&sx[c][p * 8 + 4]);

            float acc[4];
            #pragma unroll
            for (int k = 0; k < 4; k++) {
                float a = bb[k];
                a = fmaf(a0.x, w[k][0], a);
                a = fmaf(a0.y, w[k][1], a);
                a = fmaf(a0.z, w[k][2], a);
                a = fmaf(a0.w, w[k][3], a);
                a = fmaf(a1.x, w[k][4], a);
                a = fmaf(a1.y, w[k][5], a);
                a = fmaf(a1.z, w[k][6], a);
                acc[k] = a;
            }

            // Local half of row p: coalesced STG.128 (two 256B runs per warp).
            *(float4*)(ov + p * 128 + dg * 4) =
                make_float4(acc[0], acc[1], acc[2], acc[3]);

            // Half-row max over this 8-lane group (dims [32h, 32h+32) of point p).
            float m = fmaxf(fmaxf(acc[0], acc[1]), fmaxf(acc[2], acc[3]));
            m = fmaxf(m, __shfl_xor_sync(0xffffffffu, m, 1));
            m = fmaxf(m, __shfl_xor_sync(0xffffffffu, m, 2));
            m = fmaxf(m, __shfl_xor_sync(0xffffffffu, m, 4));
            if ((t & 7) == 0)
                sglob[c][2 * p + ((t >> 3) & 1)] = m;
        }

        // Commit the prefetched voxel into the other buffer (read in iter it+1).
        if (has_next) {
            sx[c ^ 1][r0 * 8 + c0] = pf0;
            if (do1) sx[c ^ 1][r1 * 8 + c1] = pf1;
        }

        __syncthreads();   // the ONE barrier: publishes sglob[c] and sx[c^1]

        // Broadcast half of every row (same coalesced pattern).
        const float4 gv = *(const float4*)(&sglob[c][dg * 4]);
        #pragma unroll
        for (int j = 0; j < 4; j++) {
            const int p = pgr * 4 + j;
            *(float4*)(ov + p * 128 + 64 + dg * 4) = gv;
        }
    }
}

extern "C" void kernel_launch(void* const* d_in, const int* in_sizes, int n_in,
                              void* d_out, int out_size)
{
    const float* x = (const float*)d_in[0];
    const float* W = (const float*)d_in[1];
    const float* b = (const float*)d_in[2];
    float* out     = (float*)d_out;

    const int B = in_sizes[0] / (PNUM * INF);       // 32768
    const int grid = (B + VPB - 1) / VPB;           // 8192
    vfe_kernel<<<grid, 128>>>(x, W, b, out, B);
}

// round 5
// speedup vs baseline: 1.0733x; 1.0280x over previous
#include <cuda_runtime.h>

#define PNUM 32
#define INF  7
#define D2   64
#define OUTF 4096   // 2*D2*PNUM floats per voxel
#define VPB  4      // voxels per block

__global__ __launch_bounds__(128, 8)
void vfe_kernel(const float* __restrict__ x,
                const float* __restrict__ W,
                const float* __restrict__ bias,
                float* __restrict__ out,
                int B)
{
    __shared__ float sx[VPB][PNUM * 8];  // all 4 voxels staged, rows padded to 8
    __shared__ float sglob[2][D2];       // parity double-buffered global vector

    const int t   = threadIdx.x;
    const int dg  = t & 15;              // dim group: dims [4*dg, 4*dg+4)
    const int pgr = t >> 4;              // point group: points [4*pgr, 4*pgr+4)

    // Per-thread weights + bias in registers, reused across all voxels.
    float w[4][INF], bb[4];
    #pragma unroll
    for (int k = 0; k < 4; k++) {
        const int d = dg * 4 + k;
        bb[k] = bias[d];
        #pragma unroll
        for (int i = 0; i < INF; i++) w[k][i] = W[d * INF + i];
    }

    const int v0 = blockIdx.x * VPB;
    float* sxf = &sx[0][0];

    // Front-loaded read burst: all VPB voxels' x (896 floats) in one pass.
    // After this, the block issues ONLY writes -> minimal R/W turnaround.
    {
        const float* xv = x + (size_t)v0 * (PNUM * INF);
        const int lim = min(VPB * PNUM * INF, (B - v0) * PNUM * INF);
        #pragma unroll
        for (int q = 0; q < 7; q++) {
            const int idx = t + q * 128;          // 0..895
            if (idx < lim) {
                const float val = __ldcs(xv + idx);
                const int r = idx / INF;          // global point row 0..127
                sxf[r * 8 + (idx - r * INF)] = val;
            }
        }
    }
    __syncthreads();

    #pragma unroll 1
    for (int it = 0; it < VPB; it++) {
        const int v = v0 + it;
        if (v >= B) break;
        const int c = it & 1;

        float* ov = out + (size_t)v * OUTF;
        const float* sxv = &sx[it][0];

        #pragma unroll
        for (int j = 0; j < 4; j++) {
            const int p = pgr * 4 + j;
            const float4 a0 = *(const float4*)(sxv + p * 8);
            const float4 a1 = *(const float4*)(sxv + p * 8 + 4);

            float acc[4];
            #pragma unroll
            for (int k = 0; k < 4; k++) {
                float a = bb[k];
                a = fmaf(a0.x, w[k][0], a);
                a = fmaf(a0.y, w[k][1], a);
                a = fmaf(a0.z, w[k][2], a);
                a = fmaf(a0.w, w[k][3], a);
                a = fmaf(a1.x, w[k][4], a);
                a = fmaf(a1.y, w[k][5], a);
                a = fmaf(a1.z, w[k][6], a);
                acc[k] = a;
            }

            // Local half of row p: coalesced, streaming (evict-first) STG.128.
            __stcs((float4*)(ov + p * 128 + dg * 4),
                   make_float4(acc[0], acc[1], acc[2], acc[3]));

            // Half-row max over this 8-lane group (dims [32h, 32h+32) of point p).
            float m = fmaxf(fmaxf(acc[0], acc[1]), fmaxf(acc[2], acc[3]));
            m = fmaxf(m, __shfl_xor_sync(0xffffffffu, m, 1));
            m = fmaxf(m, __shfl_xor_sync(0xffffffffu, m, 2));
            m = fmaxf(m, __shfl_xor_sync(0xffffffffu, m, 4));
            if ((t & 7) == 0)
                sglob[c][2 * p + ((t >> 3) & 1)] = m;
        }

        __syncthreads();   // publish sglob[c]

        // Broadcast half of every row (same coalesced streaming pattern).
        const float4 gv = *(const float4*)(&sglob[c][dg * 4]);
        #pragma unroll
        for (int j = 0; j < 4; j++) {
            const int p = pgr * 4 + j;
            __stcs((float4*)(ov + p * 128 + 64 + dg * 4), gv);
        }
    }
}

extern "C" void kernel_launch(void* const* d_in, const int* in_sizes, int n_in,
                              void* d_out, int out_size)
{
    const float* x = (const float*)d_in[0];
    const float* W = (const float*)d_in[1];
    const float* b = (const float*)d_in[2];
    float* out     = (float*)d_out;

    const int B = in_sizes[0] / (PNUM * INF);       // 32768
    const int grid = (B + VPB - 1) / VPB;           // 8192
    vfe_kernel<<<grid, 128>>>(x, W, b, out, B);
}